// round 6
// baseline (speedup 1.0000x reference)
#include <cuda_runtime.h>

#define DEVINLINE __device__ __forceinline__

constexpr int BATCH = 100;

// --- fc coefficient offsets (gates, float4 units) ---
constexpr int OFF_FC1 = 0;        // 20480
constexpr int OFF_FC2 = 20480;    // 10240
constexpr int OFF_FC3 = 30720;    // 5120
constexpr int N_FCC   = 35840;

// conv descriptor slots (float4 units): 10 slots per filter
constexpr int DESC_C1 = 0;            // 16 filters
constexpr int DESC_C2 = 16 * 10;      // 48 filters
constexpr int DESC_C3 = 64 * 10;      // 144 filters
constexpr int N_DESC  = 208 * 10;

// --- scratch (device globals; zero-initialized; halos never written) ---
__device__ float4 g_coef[N_FCC];
__device__ float4 g_desc[N_DESC];
__device__ float  g_p1[BATCH * 16 * 14 * 14];   // conv1 pooled, halo=1, [B][16][14][14]
__device__ float  g_p2[BATCH * 48 * 8 * 8];     // conv2 pooled, halo=1, [B][48][8][8]
__device__ float  g_p3[BATCH * 144 * 9];        // conv3 pooled, [B][1296] (matches ref flatten)
__device__ float  g_f1[BATCH * 20480];
__device__ float  g_f2[BATCH * 10240];

// softmax(w[16]) -> fused gate coefficients (C, A, B, D):  op = C + A*a + B*b + D*ab
DEVINLINE float4 softcoef(const float* __restrict__ w) {
    float v[16];
    float mx = -1e30f;
    #pragma unroll
    for (int i = 0; i < 16; i++) { v[i] = w[i]; mx = fmaxf(mx, v[i]); }
    float sum = 0.f;
    #pragma unroll
    for (int i = 0; i < 16; i++) { v[i] = __expf(v[i] - mx); sum += v[i]; }
    float inv = 1.0f / sum;
    #pragma unroll
    for (int i = 0; i < 16; i++) v[i] *= inv;
    float C = v[8] + v[9] + v[10] + v[11] + v[12] + v[13] + v[14] + v[15];
    float A = v[2] + v[3] + v[6] + v[7] - v[8] - v[9] - v[12] - v[13];
    float B = v[4] + v[5] + v[6] + v[7] - v[8] - v[9] - v[10] - v[11];
    float D = v[1] - v[2] - v[4] - 2.f * v[6] - v[7]
            + v[8] + 2.f * v[9] + v[11] + v[13] - v[14];
    return make_float4(C, A, B, D);
}

DEVINLINE float gate(float a, float b, float4 k) {
    return fmaf(a, fmaf(k.w, b, k.y), fmaf(k.z, b, k.x));
}

DEVINLINE float pick4(const float h[4], int i) {
    float r = h[0];
    r = (i == 1) ? h[1] : r;
    r = (i == 2) ? h[2] : r;
    r = (i == 3) ? h[3] : r;
    return r;
}

// ============================================================================
// Prep kernel: fc coefficients and conv filter descriptors (batch-major offsets).
// ============================================================================
struct PrepArgs {
    const float* fc1w; const float* fc2w; const float* fc3w;
    const int*   ci0[3]; const int* ci1[3]; const int* ci2[3];
    const float* cw0[3]; const float* cw1[3]; const float* cw2[3];
};

__constant__ int c_F[3]    = {16, 48, 144};
__constant__ int c_KS[3]   = {5, 3, 3};
__constant__ int c_CSTR[3] = {784, 196, 64};  // channel stride within one batch tile
__constant__ int c_WPAD[3] = {28, 14, 8};     // (padded) tile row width
__constant__ int c_DOFF[3] = {DESC_C1, DESC_C2, DESC_C3};

__global__ void prep_kernel(PrepArgs args) {
    int tid = blockIdx.x * blockDim.x + threadIdx.x;
    if (tid < N_FCC) {
        const float* w;
        int g;
        if (tid < OFF_FC2)      { w = args.fc1w; g = tid; }
        else if (tid < OFF_FC3) { w = args.fc2w; g = tid - OFF_FC2; }
        else                    { w = args.fc3w; g = tid - OFF_FC3; }
        g_coef[tid] = softcoef(w + (size_t)g * 16);
        return;
    }
    int j = tid - N_FCC;
    if (j >= 208) return;
    int layer, f;
    if (j < 16)      { layer = 0; f = j; }
    else if (j < 64) { layer = 1; f = j - 16; }
    else             { layer = 2; f = j - 64; }

    int F = c_F[layer], KS = c_KS[layer], CSTR = c_CSTR[layer], WP = c_WPAD[layer];
    const int* i0 = args.ci0[layer];
    const int* i1 = args.ci1[layer];
    const int* i2 = args.ci2[layer];
    float4* dst = g_desc + c_DOFF[layer] + f * 10;

    int offA[4], offB[4];
    #pragma unroll
    for (int g = 0; g < 4; g++) {
        int ta = i0[f * 4 + g], tb = i0[F * 4 + f * 4 + g];
        int ca = ta / (KS * KS), ra = ta - ca * KS * KS;
        int cb = tb / (KS * KS), rb = tb - cb * KS * KS;
        offA[g] = ca * CSTR + (ra / KS) * WP + (ra % KS);
        offB[g] = cb * CSTR + (rb / KS) * WP + (rb % KS);
        dst[2 + g] = softcoef(args.cw0[layer] + (size_t)(f * 4 + g) * 16);
    }
    dst[0] = make_float4(__int_as_float(offA[0]), __int_as_float(offA[1]),
                         __int_as_float(offA[2]), __int_as_float(offA[3]));
    dst[1] = make_float4(__int_as_float(offB[0]), __int_as_float(offB[1]),
                         __int_as_float(offB[2]), __int_as_float(offB[3]));
    int pk = 0;
    #pragma unroll
    for (int g = 0; g < 2; g++) {
        pk |= (i1[f * 2 + g] & 3) << (4 * g);
        pk |= (i1[F * 2 + f * 2 + g] & 3) << (4 * g + 2);
        dst[6 + g] = softcoef(args.cw1[layer] + (size_t)(f * 2 + g) * 16);
    }
    pk |= (i2[f] & 1) << 8;
    pk |= (i2[F + f] & 1) << 9;
    dst[8] = softcoef(args.cw2[layer] + (size_t)f * 16);
    dst[9] = make_float4(__int_as_float(pk), 0.f, 0.f, 0.f);
}

// ============================================================================
// Smem-staged conv(logic-tree) + 2x2 max-pool.
// One block = (batch, half of filter-output range). Input tile + descriptors in smem.
// ============================================================================
template <int F, int POH, int POW, int WPAD, int TILE, bool BIN,
          int OBSTR, int OFSTR, int OW, int OHALO, int DOFF, int SPLIT>
__global__ void conv_kernel(const float* __restrict__ in, float* __restrict__ out) {
    constexpr int NP = POH * POW;
    constexpr int TOTF = F * NP;
    constexpr int CHUNK = TOTF / SPLIT;
    __shared__ float  s_tile[TILE];
    __shared__ float4 s_desc[F * 10];

    int b    = blockIdx.x / SPLIT;
    int part = blockIdx.x % SPLIT;
    int tid  = threadIdx.x;

    const float* inb = in + (size_t)b * TILE;
    for (int i = tid; i < TILE; i += blockDim.x) {
        float v = inb[i];
        s_tile[i] = BIN ? ((v > 0.5f) ? 1.f : 0.f) : v;
    }
    for (int i = tid; i < F * 10; i += blockDim.x)
        s_desc[i] = g_desc[DOFF + i];
    __syncthreads();

    for (int o = part * CHUNK + tid; o < (part + 1) * CHUNK; o += blockDim.x) {
        int f = o / NP, r = o - f * NP;
        int pi = r / POW, pj = r - pi * POW;

        const float4* D = s_desc + f * 10;
        float4 s0 = D[0], s1 = D[1];
        int oa[4] = {__float_as_int(s0.x), __float_as_int(s0.y),
                     __float_as_int(s0.z), __float_as_int(s0.w)};
        int ob[4] = {__float_as_int(s1.x), __float_as_int(s1.y),
                     __float_as_int(s1.z), __float_as_int(s1.w)};
        float4 k0[4] = {D[2], D[3], D[4], D[5]};
        float4 k1[2] = {D[6], D[7]};
        float4 k2 = D[8];
        int pk = __float_as_int(D[9].x);
        int a10 = pk & 3, b10 = (pk >> 2) & 3, a11 = (pk >> 4) & 3, b11 = (pk >> 6) & 3;
        int a2 = (pk >> 8) & 1, b2 = (pk >> 9) & 1;

        float m = -1e30f;
        #pragma unroll
        for (int di = 0; di < 2; di++) {
            #pragma unroll
            for (int dj = 0; dj < 2; dj++) {
                int base = (2 * pi + di) * WPAD + 2 * pj + dj;
                float h0[4];
                #pragma unroll
                for (int g = 0; g < 4; g++) {
                    float av = s_tile[base + oa[g]];
                    float bv = s_tile[base + ob[g]];
                    h0[g] = gate(av, bv, k0[g]);
                }
                float h1[2];
                h1[0] = gate(pick4(h0, a10), pick4(h0, b10), k1[0]);
                h1[1] = gate(pick4(h0, a11), pick4(h0, b11), k1[1]);
                float v = gate(a2 ? h1[1] : h1[0], b2 ? h1[1] : h1[0], k2);
                m = fmaxf(m, v);
            }
        }
        out[(size_t)b * OBSTR + f * OFSTR + (pi + OHALO) * OW + (pj + OHALO)] = m;
    }
}

// ============================================================================
// FC layers: 4 outputs/thread, vectorized loads/stores, batch-major rows.
// ============================================================================
__global__ void fc1_kernel(const float* __restrict__ p3, const int* __restrict__ idx,
                           float* __restrict__ out) {
    int t = blockIdx.x * blockDim.x + threadIdx.x;   // 100 * 5120
    int q = t % 5120, b = t / 5120;
    int o = q * 4;
    int4 ia = *(const int4*)(idx + o);
    int4 ib = *(const int4*)(idx + 20480 + o);
    const float* row = p3 + (size_t)b * 1296;
    float4 v;
    v.x = gate(__ldg(row + ia.x), __ldg(row + ib.x), g_coef[OFF_FC1 + o]);
    v.y = gate(__ldg(row + ia.y), __ldg(row + ib.y), g_coef[OFF_FC1 + o + 1]);
    v.z = gate(__ldg(row + ia.z), __ldg(row + ib.z), g_coef[OFF_FC1 + o + 2]);
    v.w = gate(__ldg(row + ia.w), __ldg(row + ib.w), g_coef[OFF_FC1 + o + 3]);
    *(float4*)(out + (size_t)b * 20480 + o) = v;
}

__global__ void fc2_kernel(const float* __restrict__ in, const int* __restrict__ idx,
                           float* __restrict__ out) {
    int t = blockIdx.x * blockDim.x + threadIdx.x;   // 100 * 2560
    int q = t % 2560, b = t / 2560;
    int o = q * 4;
    int4 ia = *(const int4*)(idx + o);
    int4 ib = *(const int4*)(idx + 10240 + o);
    const float* row = in + (size_t)b * 20480;
    float4 v;
    v.x = gate(__ldg(row + ia.x), __ldg(row + ib.x), g_coef[OFF_FC2 + o]);
    v.y = gate(__ldg(row + ia.y), __ldg(row + ib.y), g_coef[OFF_FC2 + o + 1]);
    v.z = gate(__ldg(row + ia.z), __ldg(row + ib.z), g_coef[OFF_FC2 + o + 2]);
    v.w = gate(__ldg(row + ia.w), __ldg(row + ib.w), g_coef[OFF_FC2 + o + 3]);
    *(float4*)(out + (size_t)b * 10240 + o) = v;
}

// fc3 + GroupSum(k=10, tau=30). grid = (B, 10), block = 512.
__global__ void fc3_sum_kernel(const int* __restrict__ idx, float* __restrict__ out) {
    int b = blockIdx.x, grp = blockIdx.y;
    int t = threadIdx.x;
    int o = grp * 512 + t;
    const float* row = g_f2 + (size_t)b * 10240;
    int ia = __ldg(idx + o);
    int ib = __ldg(idx + 5120 + o);
    float v = gate(__ldg(row + ia), __ldg(row + ib), g_coef[OFF_FC3 + o]);

    __shared__ float sdata[16];
    #pragma unroll
    for (int off = 16; off; off >>= 1) v += __shfl_down_sync(0xffffffffu, v, off);
    if ((t & 31) == 0) sdata[t >> 5] = v;
    __syncthreads();
    if (t < 16) {
        float s = sdata[t];
        #pragma unroll
        for (int off = 8; off; off >>= 1) s += __shfl_down_sync(0xffffu, s, off);
        if (t == 0) out[b * 10 + grp] = s / 30.0f;
    }
}

// ============================================================================
// Launch
// ============================================================================
extern "C" void kernel_launch(void* const* d_in, const int* in_sizes, int n_in,
                              void* d_out, int out_size) {
    const float* x    = (const float*)d_in[0];
    const int*   c1i0 = (const int*)d_in[1];   const float* c1w0 = (const float*)d_in[2];
    const int*   c1i1 = (const int*)d_in[3];   const float* c1w1 = (const float*)d_in[4];
    const int*   c1i2 = (const int*)d_in[5];   const float* c1w2 = (const float*)d_in[6];
    const int*   c2i0 = (const int*)d_in[7];   const float* c2w0 = (const float*)d_in[8];
    const int*   c2i1 = (const int*)d_in[9];   const float* c2w1 = (const float*)d_in[10];
    const int*   c2i2 = (const int*)d_in[11];  const float* c2w2 = (const float*)d_in[12];
    const int*   c3i0 = (const int*)d_in[13];  const float* c3w0 = (const float*)d_in[14];
    const int*   c3i1 = (const int*)d_in[15];  const float* c3w1 = (const float*)d_in[16];
    const int*   c3i2 = (const int*)d_in[17];  const float* c3w2 = (const float*)d_in[18];
    const int*   fc1i = (const int*)d_in[19];  const float* fc1w = (const float*)d_in[20];
    const int*   fc2i = (const int*)d_in[21];  const float* fc2w = (const float*)d_in[22];
    const int*   fc3i = (const int*)d_in[23];  const float* fc3w = (const float*)d_in[24];
    float* out = (float*)d_out;

    float *p1, *p2, *p3, *f1, *f2;
    cudaGetSymbolAddress((void**)&p1, g_p1);
    cudaGetSymbolAddress((void**)&p2, g_p2);
    cudaGetSymbolAddress((void**)&p3, g_p3);
    cudaGetSymbolAddress((void**)&f1, g_f1);
    cudaGetSymbolAddress((void**)&f2, g_f2);

    // 1) prep: fc coefs + conv filter descriptors
    PrepArgs pa;
    pa.fc1w = fc1w; pa.fc2w = fc2w; pa.fc3w = fc3w;
    pa.ci0[0] = c1i0; pa.ci1[0] = c1i1; pa.ci2[0] = c1i2;
    pa.cw0[0] = c1w0; pa.cw1[0] = c1w1; pa.cw2[0] = c1w2;
    pa.ci0[1] = c2i0; pa.ci1[1] = c2i1; pa.ci2[1] = c2i2;
    pa.cw0[1] = c2w0; pa.cw1[1] = c2w1; pa.cw2[1] = c2w2;
    pa.ci0[2] = c3i0; pa.ci1[2] = c3i1; pa.ci2[2] = c3i2;
    pa.cw0[2] = c3w0; pa.cw1[2] = c3w1; pa.cw2[2] = c3w2;
    prep_kernel<<<(N_FCC + 208 + 255) / 256, 256>>>(pa);

    // 2) conv1 + pool: x[100,784] (binarize in staging) -> p1 [B][16][14][14] halo=1
    conv_kernel<16, 12, 12, 28, 784, true, 3136, 196, 14, 1, DESC_C1, 2>
        <<<BATCH * 2, 256>>>(x, p1);
    // 3) conv2 + pool: p1 [B][3136] -> p2 [B][48][8][8] halo=1
    conv_kernel<48, 6, 6, 14, 3136, false, 3072, 64, 8, 1, DESC_C2, 2>
        <<<BATCH * 2, 256>>>(p1, p2);
    // 4) conv3 + pool: p2 [B][3072] -> p3 [B][1296]
    conv_kernel<144, 3, 3, 8, 3072, false, 1296, 9, 3, 0, DESC_C3, 2>
        <<<BATCH * 2, 256>>>(p2, p3);
    // 5) fc1: 1296 -> 20480 (4 outputs/thread, raw indices)
    fc1_kernel<<<(BATCH * 5120) / 256, 256>>>(p3, fc1i, f1);
    // 6) fc2: 20480 -> 10240 (4 outputs/thread)
    fc2_kernel<<<(BATCH * 2560) / 256, 256>>>(f1, fc2i, f2);
    // 7) fc3 + group sum -> [100, 10]
    {
        dim3 grid(BATCH, 10);
        fc3_sum_kernel<<<grid, 512>>>(fc3i, out);
    }
    (void)in_sizes; (void)n_in; (void)out_size;
}

// round 7
// speedup vs baseline: 1.1079x; 1.1079x over previous
#include <cuda_runtime.h>

#define DEVINLINE __device__ __forceinline__

constexpr int BATCH = 100;

// --- fc coefficient offsets (gates, float4 units) ---
constexpr int OFF_FC1 = 0;        // 20480
constexpr int OFF_FC2 = 20480;    // 10240
constexpr int OFF_FC3 = 30720;    // 5120
constexpr int N_FCC   = 35840;

// conv descriptor slots (float4 units): 10 slots per filter
constexpr int DESC_C1 = 0;            // 16 filters
constexpr int DESC_C2 = 16 * 10;      // 48 filters
constexpr int DESC_C3 = 64 * 10;      // 144 filters
constexpr int N_DESC  = 208 * 10;

// --- scratch (device globals; zero-initialized; halos never written) ---
__device__ float4 g_coef[N_FCC];
__device__ float4 g_desc[N_DESC];
__device__ float  g_p1[BATCH * 16 * 14 * 14];   // conv1 pooled, halo=1, [B][16][14][14]
__device__ float  g_p2[BATCH * 48 * 8 * 8];     // conv2 pooled, halo=1, [B][48][8][8]
__device__ float  g_p3[BATCH * 144 * 9];        // conv3 pooled, [B][1296] (matches ref flatten)
__device__ float  g_f1[BATCH * 20480];
__device__ float  g_f2[BATCH * 10240];

// softmax(w[16]) -> fused gate coefficients (C, A, B, D):  op = C + A*a + B*b + D*ab
DEVINLINE float4 softcoef(const float* __restrict__ w) {
    float v[16];
    float mx = -1e30f;
    #pragma unroll
    for (int i = 0; i < 16; i++) { v[i] = w[i]; mx = fmaxf(mx, v[i]); }
    float sum = 0.f;
    #pragma unroll
    for (int i = 0; i < 16; i++) { v[i] = __expf(v[i] - mx); sum += v[i]; }
    float inv = 1.0f / sum;
    #pragma unroll
    for (int i = 0; i < 16; i++) v[i] *= inv;
    float C = v[8] + v[9] + v[10] + v[11] + v[12] + v[13] + v[14] + v[15];
    float A = v[2] + v[3] + v[6] + v[7] - v[8] - v[9] - v[12] - v[13];
    float B = v[4] + v[5] + v[6] + v[7] - v[8] - v[9] - v[10] - v[11];
    float D = v[1] - v[2] - v[4] - 2.f * v[6] - v[7]
            + v[8] + 2.f * v[9] + v[11] + v[13] - v[14];
    return make_float4(C, A, B, D);
}

DEVINLINE float gate(float a, float b, float4 k) {
    return fmaf(a, fmaf(k.w, b, k.y), fmaf(k.z, b, k.x));
}

DEVINLINE float pick4(const float h[4], int i) {
    float r = h[0];
    r = (i == 1) ? h[1] : r;
    r = (i == 2) ? h[2] : r;
    r = (i == 3) ? h[3] : r;
    return r;
}

// ============================================================================
// Prep kernel: fc coefficients and conv filter descriptors (batch-tile offsets).
// ============================================================================
struct PrepArgs {
    const float* fc1w; const float* fc2w; const float* fc3w;
    const int*   ci0[3]; const int* ci1[3]; const int* ci2[3];
    const float* cw0[3]; const float* cw1[3]; const float* cw2[3];
};

__constant__ int c_F[3]    = {16, 48, 144};
__constant__ int c_KS[3]   = {5, 3, 3};
__constant__ int c_CSTR[3] = {784, 196, 64};  // channel stride within one batch tile
__constant__ int c_WPAD[3] = {28, 14, 8};     // (padded) tile row width
__constant__ int c_DOFF[3] = {DESC_C1, DESC_C2, DESC_C3};

__global__ void prep_kernel(PrepArgs args) {
    int tid = blockIdx.x * blockDim.x + threadIdx.x;
    if (tid < N_FCC) {
        const float* w;
        int g;
        if (tid < OFF_FC2)      { w = args.fc1w; g = tid; }
        else if (tid < OFF_FC3) { w = args.fc2w; g = tid - OFF_FC2; }
        else                    { w = args.fc3w; g = tid - OFF_FC3; }
        g_coef[tid] = softcoef(w + (size_t)g * 16);
        return;
    }
    int j = tid - N_FCC;
    if (j >= 208) return;
    int layer, f;
    if (j < 16)      { layer = 0; f = j; }
    else if (j < 64) { layer = 1; f = j - 16; }
    else             { layer = 2; f = j - 64; }

    int F = c_F[layer], KS = c_KS[layer], CSTR = c_CSTR[layer], WP = c_WPAD[layer];
    const int* i0 = args.ci0[layer];
    const int* i1 = args.ci1[layer];
    const int* i2 = args.ci2[layer];
    float4* dst = g_desc + c_DOFF[layer] + f * 10;

    int offA[4], offB[4];
    #pragma unroll
    for (int g = 0; g < 4; g++) {
        int ta = i0[f * 4 + g], tb = i0[F * 4 + f * 4 + g];
        int ca = ta / (KS * KS), ra = ta - ca * KS * KS;
        int cb = tb / (KS * KS), rb = tb - cb * KS * KS;
        offA[g] = ca * CSTR + (ra / KS) * WP + (ra % KS);
        offB[g] = cb * CSTR + (rb / KS) * WP + (rb % KS);
        dst[2 + g] = softcoef(args.cw0[layer] + (size_t)(f * 4 + g) * 16);
    }
    dst[0] = make_float4(__int_as_float(offA[0]), __int_as_float(offA[1]),
                         __int_as_float(offA[2]), __int_as_float(offA[3]));
    dst[1] = make_float4(__int_as_float(offB[0]), __int_as_float(offB[1]),
                         __int_as_float(offB[2]), __int_as_float(offB[3]));
    int pk = 0;
    #pragma unroll
    for (int g = 0; g < 2; g++) {
        pk |= (i1[f * 2 + g] & 3) << (4 * g);
        pk |= (i1[F * 2 + f * 2 + g] & 3) << (4 * g + 2);
        dst[6 + g] = softcoef(args.cw1[layer] + (size_t)(f * 2 + g) * 16);
    }
    pk |= (i2[f] & 1) << 8;
    pk |= (i2[F + f] & 1) << 9;
    dst[8] = softcoef(args.cw2[layer] + (size_t)f * 16);
    dst[9] = make_float4(__int_as_float(pk), 0.f, 0.f, 0.f);
}

// ============================================================================
// Conv(logic-tree) + 2x2 max-pool. One thread = one pooled output.
// R2 thread mapping (b outer, f, pi, pj inner -> warp-local gather footprint),
// descriptor-driven decode (no div/mod for gathers, no boundary predicates).
// ============================================================================
template <int F, int POH, int POW, int BSTR, int WPAD, bool BIN,
          int OBSTR, int OFSTR, int OW, int OHALO, int DOFF>
__global__ void conv_kernel(const float* __restrict__ in, float* __restrict__ out) {
    constexpr int NP = POH * POW;
    constexpr int TOTAL = BATCH * F * NP;
    int tid = blockIdx.x * blockDim.x + threadIdx.x;
    if (tid >= TOTAL) return;
    int pj = tid % POW;
    int t  = tid / POW;
    int pi = t % POH; t /= POH;
    int f  = t % F;
    int b  = t / F;

    const float4* D = g_desc + DOFF + f * 10;
    float4 s0 = __ldg(D + 0), s1 = __ldg(D + 1);
    int oa[4] = {__float_as_int(s0.x), __float_as_int(s0.y),
                 __float_as_int(s0.z), __float_as_int(s0.w)};
    int ob[4] = {__float_as_int(s1.x), __float_as_int(s1.y),
                 __float_as_int(s1.z), __float_as_int(s1.w)};
    float4 k0[4] = {__ldg(D + 2), __ldg(D + 3), __ldg(D + 4), __ldg(D + 5)};
    float4 k1[2] = {__ldg(D + 6), __ldg(D + 7)};
    float4 k2 = __ldg(D + 8);
    int pk = __float_as_int(__ldg(D + 9).x);
    int a10 = pk & 3, b10 = (pk >> 2) & 3, a11 = (pk >> 4) & 3, b11 = (pk >> 6) & 3;
    int a2 = (pk >> 8) & 1, b2 = (pk >> 9) & 1;

    const float* inb = in + (size_t)b * BSTR;
    float m = -1e30f;
    #pragma unroll
    for (int di = 0; di < 2; di++) {
        #pragma unroll
        for (int dj = 0; dj < 2; dj++) {
            int base = (2 * pi + di) * WPAD + 2 * pj + dj;
            float h0[4];
            #pragma unroll
            for (int g = 0; g < 4; g++) {
                float av = __ldg(inb + base + oa[g]);
                float bv = __ldg(inb + base + ob[g]);
                if (BIN) { av = (av > 0.5f) ? 1.f : 0.f; bv = (bv > 0.5f) ? 1.f : 0.f; }
                h0[g] = gate(av, bv, k0[g]);
            }
            float h1[2];
            h1[0] = gate(pick4(h0, a10), pick4(h0, b10), k1[0]);
            h1[1] = gate(pick4(h0, a11), pick4(h0, b11), k1[1]);
            float v = gate(a2 ? h1[1] : h1[0], b2 ? h1[1] : h1[0], k2);
            m = fmaxf(m, v);
        }
    }
    out[(size_t)b * OBSTR + f * OFSTR + (pi + OHALO) * OW + (pj + OHALO)] = m;
}

// ============================================================================
// FC layers: 4 outputs/thread, vectorized loads/stores, batch-major rows.
// ============================================================================
__global__ void fc1_kernel(const float* __restrict__ p3, const int* __restrict__ idx,
                           float* __restrict__ out) {
    int t = blockIdx.x * blockDim.x + threadIdx.x;   // 100 * 5120
    int q = t % 5120, b = t / 5120;
    int o = q * 4;
    int4 ia = *(const int4*)(idx + o);
    int4 ib = *(const int4*)(idx + 20480 + o);
    const float* row = p3 + (size_t)b * 1296;
    float4 v;
    v.x = gate(__ldg(row + ia.x), __ldg(row + ib.x), g_coef[OFF_FC1 + o]);
    v.y = gate(__ldg(row + ia.y), __ldg(row + ib.y), g_coef[OFF_FC1 + o + 1]);
    v.z = gate(__ldg(row + ia.z), __ldg(row + ib.z), g_coef[OFF_FC1 + o + 2]);
    v.w = gate(__ldg(row + ia.w), __ldg(row + ib.w), g_coef[OFF_FC1 + o + 3]);
    *(float4*)(out + (size_t)b * 20480 + o) = v;
}

__global__ void fc2_kernel(const float* __restrict__ in, const int* __restrict__ idx,
                           float* __restrict__ out) {
    int t = blockIdx.x * blockDim.x + threadIdx.x;   // 100 * 2560
    int q = t % 2560, b = t / 2560;
    int o = q * 4;
    int4 ia = *(const int4*)(idx + o);
    int4 ib = *(const int4*)(idx + 10240 + o);
    const float* row = in + (size_t)b * 20480;
    float4 v;
    v.x = gate(__ldg(row + ia.x), __ldg(row + ib.x), g_coef[OFF_FC2 + o]);
    v.y = gate(__ldg(row + ia.y), __ldg(row + ib.y), g_coef[OFF_FC2 + o + 1]);
    v.z = gate(__ldg(row + ia.z), __ldg(row + ib.z), g_coef[OFF_FC2 + o + 2]);
    v.w = gate(__ldg(row + ia.w), __ldg(row + ib.w), g_coef[OFF_FC2 + o + 3]);
    *(float4*)(out + (size_t)b * 10240 + o) = v;
}

// fc3 + GroupSum(k=10, tau=30). grid = (B, 10), block = 512.
__global__ void fc3_sum_kernel(const int* __restrict__ idx, float* __restrict__ out) {
    int b = blockIdx.x, grp = blockIdx.y;
    int t = threadIdx.x;
    int o = grp * 512 + t;
    const float* row = g_f2 + (size_t)b * 10240;
    int ia = __ldg(idx + o);
    int ib = __ldg(idx + 5120 + o);
    float v = gate(__ldg(row + ia), __ldg(row + ib), g_coef[OFF_FC3 + o]);

    __shared__ float sdata[16];
    #pragma unroll
    for (int off = 16; off; off >>= 1) v += __shfl_down_sync(0xffffffffu, v, off);
    if ((t & 31) == 0) sdata[t >> 5] = v;
    __syncthreads();
    if (t < 16) {
        float s = sdata[t];
        #pragma unroll
        for (int off = 8; off; off >>= 1) s += __shfl_down_sync(0xffffu, s, off);
        if (t == 0) out[b * 10 + grp] = s / 30.0f;
    }
}

// ============================================================================
// Launch
// ============================================================================
extern "C" void kernel_launch(void* const* d_in, const int* in_sizes, int n_in,
                              void* d_out, int out_size) {
    const float* x    = (const float*)d_in[0];
    const int*   c1i0 = (const int*)d_in[1];   const float* c1w0 = (const float*)d_in[2];
    const int*   c1i1 = (const int*)d_in[3];   const float* c1w1 = (const float*)d_in[4];
    const int*   c1i2 = (const int*)d_in[5];   const float* c1w2 = (const float*)d_in[6];
    const int*   c2i0 = (const int*)d_in[7];   const float* c2w0 = (const float*)d_in[8];
    const int*   c2i1 = (const int*)d_in[9];   const float* c2w1 = (const float*)d_in[10];
    const int*   c2i2 = (const int*)d_in[11];  const float* c2w2 = (const float*)d_in[12];
    const int*   c3i0 = (const int*)d_in[13];  const float* c3w0 = (const float*)d_in[14];
    const int*   c3i1 = (const int*)d_in[15];  const float* c3w1 = (const float*)d_in[16];
    const int*   c3i2 = (const int*)d_in[17];  const float* c3w2 = (const float*)d_in[18];
    const int*   fc1i = (const int*)d_in[19];  const float* fc1w = (const float*)d_in[20];
    const int*   fc2i = (const int*)d_in[21];  const float* fc2w = (const float*)d_in[22];
    const int*   fc3i = (const int*)d_in[23];  const float* fc3w = (const float*)d_in[24];
    float* out = (float*)d_out;

    float *p1, *p2, *p3, *f1, *f2;
    cudaGetSymbolAddress((void**)&p1, g_p1);
    cudaGetSymbolAddress((void**)&p2, g_p2);
    cudaGetSymbolAddress((void**)&p3, g_p3);
    cudaGetSymbolAddress((void**)&f1, g_f1);
    cudaGetSymbolAddress((void**)&f2, g_f2);

    // 1) prep: fc coefs + conv filter descriptors
    PrepArgs pa;
    pa.fc1w = fc1w; pa.fc2w = fc2w; pa.fc3w = fc3w;
    pa.ci0[0] = c1i0; pa.ci1[0] = c1i1; pa.ci2[0] = c1i2;
    pa.cw0[0] = c1w0; pa.cw1[0] = c1w1; pa.cw2[0] = c1w2;
    pa.ci0[1] = c2i0; pa.ci1[1] = c2i1; pa.ci2[1] = c2i2;
    pa.cw0[1] = c2w0; pa.cw1[1] = c2w1; pa.cw2[1] = c2w2;
    pa.ci0[2] = c3i0; pa.ci1[2] = c3i1; pa.ci2[2] = c3i2;
    pa.cw0[2] = c3w0; pa.cw1[2] = c3w1; pa.cw2[2] = c3w2;
    prep_kernel<<<(N_FCC + 208 + 255) / 256, 256>>>(pa);

    // 2) conv1 + pool: x[100,784] (binarize at gather) -> p1 [B][16][14][14] halo=1
    {
        constexpr int TOT = BATCH * 16 * 12 * 12;
        conv_kernel<16, 12, 12, 784, 28, true, 3136, 196, 14, 1, DESC_C1>
            <<<(TOT + 255) / 256, 256>>>(x, p1);
    }
    // 3) conv2 + pool: p1 [B][3136] -> p2 [B][48][8][8] halo=1
    {
        constexpr int TOT = BATCH * 48 * 6 * 6;
        conv_kernel<48, 6, 6, 3136, 14, false, 3072, 64, 8, 1, DESC_C2>
            <<<(TOT + 255) / 256, 256>>>(p1, p2);
    }
    // 4) conv3 + pool: p2 [B][3072] -> p3 [B][1296]
    {
        constexpr int TOT = BATCH * 144 * 3 * 3;
        conv_kernel<144, 3, 3, 3072, 8, false, 1296, 9, 3, 0, DESC_C3>
            <<<(TOT + 255) / 256, 256>>>(p2, p3);
    }
    // 5) fc1: 1296 -> 20480 (4 outputs/thread, raw indices)
    fc1_kernel<<<(BATCH * 5120) / 256, 256>>>(p3, fc1i, f1);
    // 6) fc2: 20480 -> 10240 (4 outputs/thread)
    fc2_kernel<<<(BATCH * 2560) / 256, 256>>>(f1, fc2i, f2);
    // 7) fc3 + group sum -> [100, 10]
    {
        dim3 grid(BATCH, 10);
        fc3_sum_kernel<<<grid, 512>>>(fc3i, out);
    }
    (void)in_sizes; (void)n_in; (void)out_size;
}